// round 17
// baseline (speedup 1.0000x reference)
#include <cuda_runtime.h>
#include <cstdint>
#include <math.h>

// CRF NLL, B=256, T=2048, D=64 — bidirectional recursion, 2-warp chains,
// one thread per state (no shuffles, no lane-half split).
// CTA = 192 threads per batch:
//   warps 0-1: forward chain u_t (bar.sync 1,64), thread j owns state j,
//              full 64-wide i-sum: 16 LDS.128 broadcast + 32 FFMA2/step.
//   warps 2-3: backward chain c_t (bar.sync 3,64), same structure, rows of E.
//   warps 4-5: scoring (L, labels, s1+s2) concurrent with the chains.
// RN=8 renorm: each thread sums the 64 u values it loads at k==7 (no comms),
// scale folded into precomputed ex[0] at next block start. 8-deep p prefetch.
// Epilogue: Z = u_m^T (E c_{m+1}) in double; out = lzF+lzB+log(dot)-s12.

#define TT 2048
#define DD 64

typedef unsigned long long ull;

#define FMA2(d,a,b,c)  asm("fma.rn.f32x2 %0, %1, %2, %3;" : "=l"(d) : "l"(a), "l"(b), "l"(c))
#define ADD2(d,a,b)    asm("add.rn.f32x2 %0, %1, %2;"     : "=l"(d) : "l"(a), "l"(b))
#define PACK2(d,lo,hi) asm("mov.b64 %0, {%1, %2};"        : "=l"(d) : "f"(lo), "f"(hi))
#define UNPACK2(lo,hi,v) asm("mov.b64 {%0, %1}, %2;"      : "=f"(lo), "=f"(hi) : "l"(v))
#define BARF() asm volatile("bar.sync 1, 64;" ::: "memory")
#define BARB() asm volatile("bar.sync 3, 64;" ::: "memory")
#define BARS() asm volatile("bar.sync 5, 64;" ::: "memory")

__device__ __forceinline__ int warp_isum(int v) {
    #pragma unroll
    for (int s = 16; s >= 1; s >>= 1) v += __shfl_xor_sync(0xffffffffu, v, s);
    return v;
}

__global__ __launch_bounds__(192, 2)
void crf_bidir2(const float* __restrict__ p,
                const int*   __restrict__ y,
                const int*   __restrict__ mask,
                const float* __restrict__ trans,
                float*       __restrict__ out)
{
    const int b   = blockIdx.x;
    const int tid = threadIdx.x;
    const int l   = tid & 31;

    __shared__ __align__(16) float ubufF[2][DD];
    __shared__ __align__(16) float ubufB[2][DD];
    __shared__ short lab[TT];
    __shared__ float sred[2];
    __shared__ float lzF, lzB;

    // ---- every warp computes L itself (mask is tiny; L2-resident) ----
    int L;
    {
        const int4* mb4 = reinterpret_cast<const int4*>(mask + (size_t)b * TT);
        int ms = 0;
        #pragma unroll
        for (int k = 0; k < 16; k++) {
            int4 v = mb4[l + 32 * k];
            ms += v.x + v.y + v.z + v.w;
        }
        L = TT - warp_isum(ms);
    }
    const int m     = (L - 1) >> 1;   // forward does steps 1..m
    const int NBtot = L - 1 - m;      // backward matvec count (last has ex=1)
    const int NB    = NBtot - 1;      // backward emission steps

    const float* pb = p + (size_t)b * TT * DD;

    if (tid < 64) {
        // ================= forward chain: thread owns state j = tid =================
        const int j = tid;
        ull colp[32];   // (expT[2q][j], expT[2q+1][j])
        #pragma unroll
        for (int q = 0; q < 32; q++) {
            float c0 = __expf(trans[(2 * q)     * DD + j]);
            float c1 = __expf(trans[(2 * q + 1) * DD + j]);
            PACK2(colp[q], c0, c1);
        }
        ubufF[0][j] = __expf(pb[j]);

        float pf[8], exs[8];
        #pragma unroll
        for (int k = 0; k < 8; k++)
            pf[k] = (1 + k <= m) ? pb[(size_t)(1 + k) * DD + j] : 0.f;
        float Spend = 1.f, logz = 0.f;
        int base = 1;
        BARF();

        while (base + 7 <= m) {
            #pragma unroll
            for (int k = 0; k < 8; k++) exs[k] = __expf(pf[k]);
            exs[0] *= __fdividef(1.f, Spend);
            logz += __logf(Spend);
            #pragma unroll
            for (int k = 0; k < 8; k++) {
                int t2 = base + 8 + k;
                pf[k] = (t2 <= m) ? pb[(size_t)t2 * DD + j] : 0.f;
            }
            #pragma unroll
            for (int k = 0; k < 8; k++) {
                const int wb = (base + k) & 1, rb = wb ^ 1;
                const ulonglong2* ub = reinterpret_cast<const ulonglong2*>(ubufF[rb]);
                ull a0 = 0, a1 = 0, a2 = 0, a3 = 0, s0 = 0, s1 = 0;
                #pragma unroll
                for (int q = 0; q < 8; q++) {
                    ulonglong2 uA = ub[2 * q];
                    ulonglong2 uB = ub[2 * q + 1];
                    FMA2(a0, uA.x, colp[4 * q + 0], a0);
                    FMA2(a1, uA.y, colp[4 * q + 1], a1);
                    FMA2(a2, uB.x, colp[4 * q + 2], a2);
                    FMA2(a3, uB.y, colp[4 * q + 3], a3);
                    if (k == 7) {
                        ADD2(s0, s0, uA.x); ADD2(s0, s0, uB.x);
                        ADD2(s1, s1, uA.y); ADD2(s1, s1, uB.y);
                    }
                }
                ADD2(a0, a0, a1); ADD2(a2, a2, a3); ADD2(a0, a0, a2);
                float lo, hi; UNPACK2(lo, hi, a0);
                ubufF[wb][j] = exs[k] * (lo + hi);
                if (k == 7) {
                    ADD2(s0, s0, s1);
                    float slo, shi; UNPACK2(slo, shi, s0);
                    Spend = slo + shi;
                }
                BARF();
            }
            base += 8;
        }
        if (base <= m) {
            const float rinv = __fdividef(1.f, Spend);
            logz += __logf(Spend);
            for (int t = base; t <= m; t++) {
                const int k = t - base;
                float ex = __expf(pf[k]);
                if (k == 0) ex *= rinv;
                const int wb = t & 1, rb = wb ^ 1;
                const ulonglong2* ub = reinterpret_cast<const ulonglong2*>(ubufF[rb]);
                ull a0 = 0, a1 = 0, a2 = 0, a3 = 0;
                #pragma unroll
                for (int q = 0; q < 8; q++) {
                    ulonglong2 uA = ub[2 * q];
                    ulonglong2 uB = ub[2 * q + 1];
                    FMA2(a0, uA.x, colp[4 * q + 0], a0);
                    FMA2(a1, uA.y, colp[4 * q + 1], a1);
                    FMA2(a2, uB.x, colp[4 * q + 2], a2);
                    FMA2(a3, uB.y, colp[4 * q + 3], a3);
                }
                ADD2(a0, a0, a1); ADD2(a2, a2, a3); ADD2(a0, a0, a2);
                float lo, hi; UNPACK2(lo, hi, a0);
                ubufF[wb][j] = ex * (lo + hi);
                BARF();
            }
        }
        if (tid == 0) lzF = logz;
    } else if (tid < 128) {
        // ================= backward chain: thread owns state j = tid-64 =================
        const int j = tid - 64;
        ull colp[32];   // (expT[j][2q], expT[j][2q+1])
        #pragma unroll
        for (int q = 0; q < 32; q++) {
            float c0 = __expf(trans[j * DD + 2 * q]);
            float c1 = __expf(trans[j * DD + 2 * q + 1]);
            PACK2(colp[q], c0, c1);
        }
        ubufB[0][j] = __expf(pb[(size_t)(L - 1) * DD + j]);

        float pf[8], exs[8];
        #pragma unroll
        for (int k = 0; k < 8; k++)
            pf[k] = (1 + k <= NB) ? pb[(size_t)(L - 2 - k) * DD + j] : 0.f;
        float Spend = 1.f, logz = 0.f;
        int base = 1;
        BARB();

        while (base + 7 <= NBtot) {
            #pragma unroll
            for (int k = 0; k < 8; k++)
                exs[k] = (base + k <= NB) ? __expf(pf[k]) : 1.f;
            exs[0] *= __fdividef(1.f, Spend);
            logz += __logf(Spend);
            #pragma unroll
            for (int k = 0; k < 8; k++) {
                int n2 = base + 8 + k;
                pf[k] = (n2 <= NB) ? pb[(size_t)(L - 1 - n2) * DD + j] : 0.f;
            }
            #pragma unroll
            for (int k = 0; k < 8; k++) {
                const int wb = (base + k) & 1, rb = wb ^ 1;
                const ulonglong2* ub = reinterpret_cast<const ulonglong2*>(ubufB[rb]);
                ull a0 = 0, a1 = 0, a2 = 0, a3 = 0, s0 = 0, s1 = 0;
                #pragma unroll
                for (int q = 0; q < 8; q++) {
                    ulonglong2 uA = ub[2 * q];
                    ulonglong2 uB = ub[2 * q + 1];
                    FMA2(a0, uA.x, colp[4 * q + 0], a0);
                    FMA2(a1, uA.y, colp[4 * q + 1], a1);
                    FMA2(a2, uB.x, colp[4 * q + 2], a2);
                    FMA2(a3, uB.y, colp[4 * q + 3], a3);
                    if (k == 7) {
                        ADD2(s0, s0, uA.x); ADD2(s0, s0, uB.x);
                        ADD2(s1, s1, uA.y); ADD2(s1, s1, uB.y);
                    }
                }
                ADD2(a0, a0, a1); ADD2(a2, a2, a3); ADD2(a0, a0, a2);
                float lo, hi; UNPACK2(lo, hi, a0);
                ubufB[wb][j] = exs[k] * (lo + hi);
                if (k == 7) {
                    ADD2(s0, s0, s1);
                    float slo, shi; UNPACK2(slo, shi, s0);
                    Spend = slo + shi;
                }
                BARB();
            }
            base += 8;
        }
        if (base <= NBtot) {
            const float rinv = __fdividef(1.f, Spend);
            logz += __logf(Spend);
            for (int n = base; n <= NBtot; n++) {
                const int k = n - base;
                float ex = (n <= NB) ? __expf(pf[k]) : 1.f;
                if (k == 0) ex *= rinv;
                const int wb = n & 1, rb = wb ^ 1;
                const ulonglong2* ub = reinterpret_cast<const ulonglong2*>(ubufB[rb]);
                ull a0 = 0, a1 = 0, a2 = 0, a3 = 0;
                #pragma unroll
                for (int q = 0; q < 8; q++) {
                    ulonglong2 uA = ub[2 * q];
                    ulonglong2 uB = ub[2 * q + 1];
                    FMA2(a0, uA.x, colp[4 * q + 0], a0);
                    FMA2(a1, uA.y, colp[4 * q + 1], a1);
                    FMA2(a2, uB.x, colp[4 * q + 2], a2);
                    FMA2(a3, uB.y, colp[4 * q + 3], a3);
                }
                ADD2(a0, a0, a1); ADD2(a2, a2, a3); ADD2(a0, a0, a2);
                float lo, hi; UNPACK2(lo, hi, a0);
                ubufB[wb][j] = ex * (lo + hi);
                BARB();
            }
        }
        if (tid == 64) lzB = logz;
    } else {
        // ================= scoring warps (concurrent with chains) =================
        const int idx = tid - 128;      // 0..63
        const int4* yb4 = reinterpret_cast<const int4*>(y + (size_t)b * TT * DD);
        for (int t = idx; t < TT; t += 64) {
            const int4* row = yb4 + (size_t)t * 16;
            int lv = 0;
            #pragma unroll
            for (int k = 0; k < 16; k++) {
                int4 v = row[k];
                lv += v.x * (4 * k) + v.y * (4 * k + 1) + v.z * (4 * k + 2) + v.w * (4 * k + 3);
            }
            lab[t] = (short)lv;
        }
        BARS();
        float s = 0.f;
        for (int t = idx; t < L; t += 64) {
            int lt = lab[t];
            s += pb[(size_t)t * DD + lt];
            if (t < L - 1) s += trans[lt * DD + lab[t + 1]];
        }
        #pragma unroll
        for (int ss = 16; ss >= 1; ss >>= 1) s += __shfl_xor_sync(0xffffffffu, s, ss);
        if (l == 0) sred[(tid >> 5) - 4] = s;
    }
    __syncthreads();

    // ================= epilogue: Z = u_m^T d (double) =================
    if (tid < 32) {
        const int fb = m & 1;
        const int db = NBtot & 1;
        double prod = (double)ubufF[fb][l]      * (double)ubufB[db][l]
                    + (double)ubufF[fb][l + 32] * (double)ubufB[db][l + 32];
        #pragma unroll
        for (int s = 16; s >= 1; s >>= 1)
            prod += __shfl_xor_sync(0xffffffffu, prod, s);
        if (l == 0)
            out[b] = lzF + lzB + (float)log(prod) - (sred[0] + sred[1]);
    }
}

extern "C" void kernel_launch(void* const* d_in, const int* in_sizes, int n_in,
                              void* d_out, int out_size) {
    const float* p     = (const float*)d_in[0];
    const int*   y     = (const int*)d_in[1];
    const int*   mask  = (const int*)d_in[2];
    const float* trans = (const float*)d_in[3];
    float* out = (float*)d_out;
    (void)in_sizes; (void)n_in; (void)out_size;
    crf_bidir2<<<256, 192>>>(p, y, mask, trans, out);
}